// round 3
// baseline (speedup 1.0000x reference)
#include <cuda_runtime.h>
#include <math.h>

// out_b[k] = p(x_b) . S[k] + beta * x_b[k] + v0[k]
// p(x) = (x0^2, x1^2, x2^2, x0x1, x0x2, x1x2)
// smem const layout: c[0..17]=S (row k = c[6k..6k+5]), c[18]=beta, c[19..21]=v0

__device__ __forceinline__ void eval3(const float* __restrict__ c,
                                      float x0, float x1, float x2,
                                      float& o0, float& o1, float& o2)
{
    float p0 = x0 * x0, p1 = x1 * x1, p2 = x2 * x2;
    float p3 = x0 * x1, p4 = x0 * x2, p5 = x1 * x2;
    float beta = c[18];
    o0 = fmaf(c[0],  p0, fmaf(c[1],  p1, fmaf(c[2],  p2, fmaf(c[3],  p3, fmaf(c[4],  p4, fmaf(c[5],  p5, fmaf(beta, x0, c[19])))))));
    o1 = fmaf(c[6],  p0, fmaf(c[7],  p1, fmaf(c[8],  p2, fmaf(c[9],  p3, fmaf(c[10], p4, fmaf(c[11], p5, fmaf(beta, x1, c[20])))))));
    o2 = fmaf(c[12], p0, fmaf(c[13], p1, fmaf(c[14], p2, fmaf(c[15], p3, fmaf(c[16], p4, fmaf(c[17], p5, fmaf(beta, x2, c[21])))))));
}

__global__ void fused_kernel(const float* __restrict__ t_p,
                             const float* __restrict__ xin,
                             const float* __restrict__ R,
                             const float* __restrict__ m,
                             const float* __restrict__ Wl1, const float* __restrict__ Wd1,
                             const float* __restrict__ Wl2, const float* __restrict__ Wd2,
                             const float* __restrict__ Wl3, const float* __restrict__ Wd3,
                             const float* __restrict__ Wl4, const float* __restrict__ Wd4,
                             const float* __restrict__ Wb1_lin,
                             const float* __restrict__ Wb1_d1, const float* __restrict__ Wb1_d2,
                             const float* __restrict__ Wb2_lin,
                             const float* __restrict__ Wb2_d1, const float* __restrict__ Wb2_d2,
                             const float* __restrict__ Wout,
                             float* __restrict__ out, int B)
{
    const int F = 20;
    __shared__ float mm_s[20][3];
    __shared__ float M_s[4][3][3];
    __shared__ float c_s[24];

    int tid = threadIdx.x;
    int i   = blockIdx.x * blockDim.x + tid;
    int n8  = B >> 3;

    // ---- Pre-issue the streaming loads (independent of setup) ----
    const float4* in4 = (const float4*)xin;
    float4 v0x, v1x, v2x, v3x, v4x, v5x;
    bool active = (i < n8);
    if (active) {
        const float4* p = in4 + 6 * (size_t)i;
        v0x = p[0]; v1x = p[1]; v2x = p[2]; v3x = p[3]; v4x = p[4]; v5x = p[5];
    }

    // ---- Per-block setup on warp 0 ----
    if (tid < 32) {
        int lane = tid;

        // Phase A: mm[f][k] = sum_j R[k][j] * m[j][f]
        if (lane < F) {
            float m0 = m[0 * F + lane], m1 = m[1 * F + lane], m2 = m[2 * F + lane];
#pragma unroll
            for (int k = 0; k < 3; k++)
                mm_s[lane][k] = fmaf(R[k * 3 + 0], m0, fmaf(R[k * 3 + 1], m1, R[k * 3 + 2] * m2));
        }

        // Phase B: channel-collapse scalars (warp reduce)
        float a1 = 0.f, b1 = 0.f, a2 = 0.f, b2 = 0.f;
        if (lane < F) {
            float s11 = 0.f, s12 = 0.f, s21 = 0.f, s22 = 0.f;
#pragma unroll 5
            for (int g = 0; g < F; g++) {
                float l1 = Wb1_lin[g], l2 = Wb2_lin[g];
                s11 = fmaf(Wb1_d1[lane * F + g], l1, s11);
                s12 = fmaf(Wb1_d2[lane * F + g], l1, s12);
                s21 = fmaf(Wb2_d1[lane * F + g], l2, s21);
                s22 = fmaf(Wb2_d2[lane * F + g], l2, s22);
            }
            float wo = Wout[lane];
            a1 = wo * s11 * s12;
            b1 = wo * Wb1_lin[lane];
            a2 = wo * s21 * s22;
            b2 = wo * Wb2_lin[lane];
        }
#pragma unroll
        for (int off = 16; off > 0; off >>= 1) {
            a1 += __shfl_down_sync(0xffffffffu, a1, off);
            b1 += __shfl_down_sync(0xffffffffu, b1, off);
            a2 += __shfl_down_sync(0xffffffffu, a2, off);
            b2 += __shfl_down_sync(0xffffffffu, b2, off);
        }
        __syncwarp();

        // Phase C: map_m chains -> M[i] = o^T o  (4 lanes)
        if (lane < 4) {
            const float* Wl = (lane == 0) ? Wl1 : (lane == 1) ? Wl2 : (lane == 2) ? Wl3 : Wl4;
            const float* Wd = (lane == 0) ? Wd1 : (lane == 1) ? Wd2 : (lane == 2) ? Wd3 : Wd4;
            float y0[3][3], d[3][3], o[3][3];
#pragma unroll
            for (int a = 0; a < 3; a++)
#pragma unroll
                for (int k = 0; k < 3; k++) {
                    float s = 0.f;
                    for (int f = 0; f < F; f++) s = fmaf(Wl[a * F + f], mm_s[f][k], s);
                    y0[a][k] = s;
                }
#pragma unroll
            for (int p = 0; p < 3; p++)
#pragma unroll
                for (int k = 0; k < 3; k++)
                    d[p][k] = fmaf(Wd[p * 3 + 0], y0[0][k],
                              fmaf(Wd[p * 3 + 1], y0[1][k], Wd[p * 3 + 2] * y0[2][k]));
#pragma unroll
            for (int f = 0; f < 3; f++) {
                float xd = 0.f, dd = 0.f;
#pragma unroll
                for (int k = 0; k < 3; k++) { xd = fmaf(y0[f][k], d[f][k], xd); dd = fmaf(d[f][k], d[f][k], dd); }
                float kf_xd = -2.f * xd;
                float kf_dd = -2.f * dd;
                float denom = fminf(kf_dd, -1e-12f);
                float coef  = (kf_xd < 0.f) ? 0.f : (kf_xd / denom);
#pragma unroll
                for (int k = 0; k < 3; k++) o[f][k] = fmaf(-coef, d[f][k], y0[f][k]);
            }
#pragma unroll
            for (int k = 0; k < 3; k++)
#pragma unroll
                for (int k2 = 0; k2 < 3; k2++)
                    M_s[lane][k][k2] = fmaf(o[0][k], o[0][k2],
                                       fmaf(o[1][k], o[1][k2], o[2][k] * o[2][k2]));
        }
        __syncwarp();

        // Phase D: assemble the 22 constants (lane 0)
        if (lane == 0) {
            float t  = t_p[0];
            float st = sinf(t), ct = cosf(t);
            float base[3] = {10.f * st, 10.f * ct, 10.f * st};
            float u[3];
#pragma unroll
            for (int k = 0; k < 3; k++)
                u[k] = fmaf(R[k * 3 + 0], base[0], fmaf(R[k * 3 + 1], base[1], R[k * 3 + 2] * base[2]));

            float y3[3], y4[3];
#pragma unroll
            for (int k = 0; k < 3; k++) {
                y3[k] = fmaf(M_s[2][k][0], u[0], fmaf(M_s[2][k][1], u[1], M_s[2][k][2] * u[2]));
                y4[k] = fmaf(M_s[3][k][0], u[0], fmaf(M_s[3][k][1], u[1], M_s[3][k][2] * u[2]));
            }
            float cru0 = y3[1] * y4[2] - y3[2] * y4[1];
            float cru1 = y3[2] * y4[0] - y3[0] * y4[2];
            float cru2 = y3[0] * y4[1] - y3[1] * y4[0];

            c_s[18] = b1;
            c_s[19] = fmaf(a2, cru0, b2 * u[0]);
            c_s[20] = fmaf(a2, cru1, b2 * u[1]);
            c_s[21] = fmaf(a2, cru2, b2 * u[2]);
            c_s[22] = 0.f; c_s[23] = 0.f;

#pragma unroll
            for (int k = 0; k < 3; k++) {
                int k1 = (k + 1) % 3, k2 = (k + 2) % 3;
                float Q[3][3];
#pragma unroll
                for (int ii = 0; ii < 3; ii++)
#pragma unroll
                    for (int jj = 0; jj < 3; jj++)
                        Q[ii][jj] = a1 * (M_s[0][k1][ii] * M_s[1][k2][jj]
                                          - M_s[0][k2][ii] * M_s[1][k1][jj]);
                c_s[k * 6 + 0] = Q[0][0];
                c_s[k * 6 + 1] = Q[1][1];
                c_s[k * 6 + 2] = Q[2][2];
                c_s[k * 6 + 3] = Q[0][1] + Q[1][0];
                c_s[k * 6 + 4] = Q[0][2] + Q[2][0];
                c_s[k * 6 + 5] = Q[1][2] + Q[2][1];
            }
        }
    }
    __syncthreads();

    const float* c = c_s;

    if (active) {
        float r0, r1, r2, r3, r4, r5, r6, r7, r8, r9, r10, r11;
        float r12, r13, r14, r15, r16, r17, r18, r19, r20, r21, r22, r23;
        eval3(c, v0x.x, v0x.y, v0x.z, r0,  r1,  r2);
        eval3(c, v0x.w, v1x.x, v1x.y, r3,  r4,  r5);
        eval3(c, v1x.z, v1x.w, v2x.x, r6,  r7,  r8);
        eval3(c, v2x.y, v2x.z, v2x.w, r9,  r10, r11);
        eval3(c, v3x.x, v3x.y, v3x.z, r12, r13, r14);
        eval3(c, v3x.w, v4x.x, v4x.y, r15, r16, r17);
        eval3(c, v4x.z, v4x.w, v5x.x, r18, r19, r20);
        eval3(c, v5x.y, v5x.z, v5x.w, r21, r22, r23);

        float4* q = (float4*)out + 6 * (size_t)i;
        q[0] = make_float4(r0,  r1,  r2,  r3);
        q[1] = make_float4(r4,  r5,  r6,  r7);
        q[2] = make_float4(r8,  r9,  r10, r11);
        q[3] = make_float4(r12, r13, r14, r15);
        q[4] = make_float4(r16, r17, r18, r19);
        q[5] = make_float4(r20, r21, r22, r23);
    }

    // tail (B not divisible by 8)
    if (i == n8) {
        for (int e = 8 * n8; e < B; e++) {
            float o0, o1, o2;
            eval3(c, xin[3 * e + 0], xin[3 * e + 1], xin[3 * e + 2], o0, o1, o2);
            out[3 * e + 0] = o0;
            out[3 * e + 1] = o1;
            out[3 * e + 2] = o2;
        }
    }
}

extern "C" void kernel_launch(void* const* d_in, const int* in_sizes, int n_in,
                              void* d_out, int out_size)
{
    const float* t_p     = (const float*)d_in[0];
    const float* x       = (const float*)d_in[1];
    const float* R       = (const float*)d_in[2];
    const float* m       = (const float*)d_in[3];
    const float* Wl1     = (const float*)d_in[4];
    const float* Wd1     = (const float*)d_in[5];
    const float* Wl2     = (const float*)d_in[6];
    const float* Wd2     = (const float*)d_in[7];
    const float* Wl3     = (const float*)d_in[8];
    const float* Wd3     = (const float*)d_in[9];
    const float* Wl4     = (const float*)d_in[10];
    const float* Wd4     = (const float*)d_in[11];
    const float* Wb1_lin = (const float*)d_in[12];
    const float* Wb1_d1  = (const float*)d_in[13];
    const float* Wb1_d2  = (const float*)d_in[14];
    const float* Wb2_lin = (const float*)d_in[15];
    const float* Wb2_d1  = (const float*)d_in[16];
    const float* Wb2_d2  = (const float*)d_in[17];
    const float* Wout    = (const float*)d_in[18];

    int B = in_sizes[1] / 3;

    int n8      = B >> 3;
    int threads = n8 + 1;          // +1 thread for the tail
    int block   = 128;
    int grid    = (threads + block - 1) / block;

    fused_kernel<<<grid, block>>>(t_p, x, R, m, Wl1, Wd1, Wl2, Wd2, Wl3, Wd3, Wl4, Wd4,
                                  Wb1_lin, Wb1_d1, Wb1_d2, Wb2_lin, Wb2_d1, Wb2_d2, Wout,
                                  (float*)d_out, B);
}